// round 3
// baseline (speedup 1.0000x reference)
#include <cuda_runtime.h>
#include <cstdint>

// Problem constants
#define BB      4
#define GROUPS  2048           // B * N/4
#define MM      64             // G1*G2 grid cells
#define CC      128            // channels
#define TOK     8192           // MM*CC floats per token
#define RK      8
#define RRR     512            // RK^3
#define MASKN   524288         // B*N*M mask elements (bytes scanned)

// Scratch (__device__ globals; no allocation allowed)
__device__ float g_s [(size_t)GROUPS * TOK];  // 64 MB group sums
__device__ float g_t1[(size_t)GROUPS * RRR];  // 4 MB  T1[g][(a,d,F)]
__device__ float g_u2[(size_t)GROUPS * RRR];  // 4 MB  U2[g][(o,p,C)]
__device__ float g_wa[RRR * RRR / 512 * 512]; // 1 MB  ping
__device__ float g_wb[RRR * RRR / 512 * 512]; // 1 MB  pong
__device__ float g_w4[RRR * RRR / 512 * 512]; // 1 MB  folded operator
__device__ int   g_maskmode;                  // 0=int32, 1=uint8, 2=float32

// ---------------------------------------------------------------------------
// Kernel 0: detect mask dtype (bool may be marshalled as u8/i32/f32).
// ---------------------------------------------------------------------------
__global__ void __launch_bounds__(1024) k0_detect_mask(const unsigned char* __restrict__ mask)
{
    __shared__ int s_ge2, s_odd;
    if (threadIdx.x == 0) { s_ge2 = 0; s_odd = 0; }
    __syncthreads();
    const uint4* p = (const uint4*)mask;
    unsigned acc = 0;
    for (int i = threadIdx.x; i < MASKN / 16; i += 1024) {
        uint4 v = p[i];
        acc |= (v.x | v.y | v.z | v.w);
    }
    if (acc & 0xFEFEFEFEu) atomicOr(&s_ge2, 1);   // any byte >= 2 -> float
    if (acc & 0xFFFFFF00u) atomicOr(&s_odd, 1);   // nonzero off-word byte -> u8
    __syncthreads();
    if (threadIdx.x == 0) g_maskmode = s_ge2 ? 2 : (s_odd ? 1 : 0);
}

// ---------------------------------------------------------------------------
// Precompute: fold the 4 small factors into the core (4 passes, 262144 elems).
// core[A,B,C,D,E,F] row-major. Each pass contracts one 8-dim axis.
// ---------------------------------------------------------------------------
__global__ void __launch_bounds__(256) p1_foldA(const float* __restrict__ core,
                                                const float* __restrict__ f) // out_f0 (o,A)
{
    int idx = blockIdx.x * 256 + threadIdx.x;        // (o, BCDEF)
    int o = idx >> 15, rest = idx & 32767;
    float acc = 0.f;
    #pragma unroll
    for (int A = 0; A < 8; A++) acc += f[o * 8 + A] * __ldg(&core[A * 32768 + rest]);
    g_wa[idx] = acc;
}
__global__ void __launch_bounds__(256) p2_foldB(const float* __restrict__ f) // out_f1 (p,B)
{
    int idx = blockIdx.x * 256 + threadIdx.x;        // (o, p, CDEF)
    int o = idx >> 15, p = (idx >> 12) & 7, rest = idx & 4095;
    float acc = 0.f;
    #pragma unroll
    for (int B = 0; B < 8; B++) acc += f[p * 8 + B] * g_wa[o * 32768 + B * 4096 + rest];
    g_wb[idx] = acc;
}
__global__ void __launch_bounds__(256) p3_foldD(const float* __restrict__ f) // in_f0 (a,D)
{
    int idx = blockIdx.x * 256 + threadIdx.x;        // (opC, a, EF)
    int opC = idx >> 9, a = (idx >> 6) & 7, EF = idx & 63;
    float acc = 0.f;
    #pragma unroll
    for (int D = 0; D < 8; D++) acc += f[a * 8 + D] * g_wb[opC * 512 + D * 64 + EF];
    g_wa[idx] = acc;
}
__global__ void __launch_bounds__(256) p4_foldE(const float* __restrict__ f) // in_f1 (d,E)
{
    int idx = blockIdx.x * 256 + threadIdx.x;        // (opC, a, d, F)
    int opC = idx >> 9, a = (idx >> 6) & 7, d = (idx >> 3) & 7, F = idx & 7;
    float acc = 0.f;
    #pragma unroll
    for (int E = 0; E < 8; E++) acc += f[d * 8 + E] * g_wa[opC * 512 + a * 64 + E * 8 + F];
    g_w4[idx] = acc;
}

// ---------------------------------------------------------------------------
// Kernel 1: per group: s = sum of 4 tokens -> scratch; T1[m][F] via fused
// warp-shuffle reduction (no big smem tile). grid=2048, 256 threads.
// ---------------------------------------------------------------------------
__global__ void __launch_bounds__(256) k1_reduce_project(
    const float* __restrict__ x,
    const float* __restrict__ in_f2)   // (128,8)
{
    __shared__ float f2q[RK * CC];     // f2q[F*128 + e] (transposed)
    __shared__ float t1s[RRR];         // t1[m*8+F]

    const int tid = threadIdx.x, lane = tid & 31;
    const size_t gidx = blockIdx.x;

    #pragma unroll
    for (int i = tid; i < CC * RK; i += 256) {
        int e = i >> 3, F = i & 7;
        f2q[F * CC + e] = in_f2[i];
    }
    __syncthreads();

    const float4* xb = (const float4*)(x + gidx * (size_t)(4 * TOK));
    float4*       sg = (float4*)(g_s + gidx * (size_t)TOK);

    #pragma unroll
    for (int it = 0; it < 8; it++) {
        int i = tid + it * 256;                 // float4 idx; m = i>>5, lane = e-quad
        float4 v0 = xb[i];
        float4 v1 = xb[i + 2048];
        float4 v2 = xb[i + 4096];
        float4 v3 = xb[i + 6144];
        float4 r;
        r.x = (v0.x + v1.x) + (v2.x + v3.x);
        r.y = (v0.y + v1.y) + (v2.y + v3.y);
        r.z = (v0.z + v1.z) + (v2.z + v3.z);
        r.w = (v0.w + v1.w) + (v2.w + v3.w);
        sg[i] = r;
        float acc[8];
        #pragma unroll
        for (int F = 0; F < 8; F++) {
            float4 f = *(const float4*)&f2q[F * CC + lane * 4];  // conflict-free
            acc[F] = r.x * f.x + r.y * f.y + r.z * f.z + r.w * f.w;
        }
        #pragma unroll
        for (int off = 16; off >= 1; off >>= 1)
            #pragma unroll
            for (int F = 0; F < 8; F++)
                acc[F] += __shfl_xor_sync(0xffffffffu, acc[F], off);
        if (lane == 0) {
            int m = i >> 5;
            #pragma unroll
            for (int F = 0; F < 8; F++) t1s[m * 8 + F] = acc[F];
        }
    }
    __syncthreads();
    float4* t1g = (float4*)(g_t1 + gidx * (size_t)RRR);
    if (tid < 128) t1g[tid] = ((const float4*)t1s)[tid];
}

// ---------------------------------------------------------------------------
// Kernel 2: U2 = T1 @ W4^T  (2048x512)@(512x512)^T, fp32 SIMT 64x64 tiles.
// ---------------------------------------------------------------------------
__global__ void __launch_bounds__(256) k2_core_gemm()
{
    __shared__ float As[16][68];
    __shared__ float Bs[16][68];

    const int tid = threadIdx.x;
    const int bm = blockIdx.x * 64;
    const int bn = blockIdx.y * 64;
    const int tx = tid & 15, ty = tid >> 4;
    const int lr = tid >> 2;
    const int lk = (tid & 3) << 2;

    float acc[4][4];
    #pragma unroll
    for (int i = 0; i < 4; i++)
        #pragma unroll
        for (int j = 0; j < 4; j++) acc[i][j] = 0.f;

    for (int k0 = 0; k0 < RRR; k0 += 16) {
        float4 av = *(const float4*)(g_t1 + (size_t)(bm + lr) * RRR + k0 + lk);
        float4 bv = *(const float4*)(g_w4 + (size_t)(bn + lr) * RRR + k0 + lk);
        __syncthreads();
        As[lk + 0][lr] = av.x; As[lk + 1][lr] = av.y;
        As[lk + 2][lr] = av.z; As[lk + 3][lr] = av.w;
        Bs[lk + 0][lr] = bv.x; Bs[lk + 1][lr] = bv.y;
        Bs[lk + 2][lr] = bv.z; Bs[lk + 3][lr] = bv.w;
        __syncthreads();
        #pragma unroll
        for (int k = 0; k < 16; k++) {
            float a[4], b[4];
            #pragma unroll
            for (int i = 0; i < 4; i++) a[i] = As[k][ty * 4 + i];
            #pragma unroll
            for (int j = 0; j < 4; j++) b[j] = Bs[k][tx * 4 + j];
            #pragma unroll
            for (int i = 0; i < 4; i++)
                #pragma unroll
                for (int j = 0; j < 4; j++) acc[i][j] += a[i] * b[j];
        }
    }
    #pragma unroll
    for (int i = 0; i < 4; i++)
        #pragma unroll
        for (int j = 0; j < 4; j++)
            g_u2[(size_t)(bm + ty * 4 + i) * RRR + bn + tx * 4 + j] = acc[i][j];
}

// ---------------------------------------------------------------------------
// Kernel 3: pure stream: out[m][q] = (sum_C u2[m][C]*out_f2[q][C] + s) * invw.
// grid=2048, 256 threads, low regs -> high occupancy, DRAM-bound.
// ---------------------------------------------------------------------------
__global__ void __launch_bounds__(256) k3_stream(
    const float* __restrict__ out_f2,  // (128,8)
    const void*  __restrict__ maskp,
    float* __restrict__ out)
{
    __shared__ float f2t[RK * CC];     // f2t[Cr*128 + q]
    __shared__ float u2s[RRR];         // u2[m*8+Cr]
    __shared__ float invw[MM];

    const int tid = threadIdx.x;
    const size_t gidx = blockIdx.x;

    if (tid < 128)
        ((float4*)u2s)[tid] = ((const float4*)(g_u2 + gidx * (size_t)RRR))[tid];
    #pragma unroll
    for (int i = tid; i < RK * CC; i += 256) {
        int q = i >> 3, Cr = i & 7;
        f2t[Cr * CC + q] = out_f2[i];
    }
    if (tid < 64) {
        int mode = g_maskmode;
        int w;
        if (mode == 1) {
            const unsigned char* mb = (const unsigned char*)maskp + gidx * (size_t)256;
            w = (mb[tid] ? 0 : 1) + (mb[tid + 64] ? 0 : 1)
              + (mb[tid + 128] ? 0 : 1) + (mb[tid + 192] ? 0 : 1);
        } else if (mode == 0) {
            const int* mi = (const int*)maskp + gidx * (size_t)256;
            w = (mi[tid] ? 0 : 1) + (mi[tid + 64] ? 0 : 1)
              + (mi[tid + 128] ? 0 : 1) + (mi[tid + 192] ? 0 : 1);
        } else {
            const float* mf = (const float*)maskp + gidx * (size_t)256;
            w = (mf[tid] != 0.f ? 0 : 1) + (mf[tid + 64] != 0.f ? 0 : 1)
              + (mf[tid + 128] != 0.f ? 0 : 1) + (mf[tid + 192] != 0.f ? 0 : 1);
        }
        invw[tid] = (w > 0) ? 1.0f / ((float)w + 1e-10f) : 0.0f;
    }
    __syncthreads();

    const float4* sg = (const float4*)(g_s + gidx * (size_t)TOK);
    float4*       og = (float4*)(out + gidx * (size_t)TOK);
    #pragma unroll
    for (int it = 0; it < 8; it++) {
        int i  = tid + it * 256;
        int m  = i >> 5;
        int q0 = (i & 31) << 2;
        float4 sv = sg[i];
        float r0 = 0.f, r1 = 0.f, r2 = 0.f, r3 = 0.f;
        #pragma unroll
        for (int Cr = 0; Cr < 8; Cr++) {
            float u = u2s[m * 8 + Cr];                      // warp-uniform broadcast
            float4 f = *(const float4*)&f2t[Cr * CC + q0];  // conflict-free
            r0 += u * f.x; r1 += u * f.y; r2 += u * f.z; r3 += u * f.w;
        }
        float iw = invw[m];
        float4 ov;
        ov.x = (r0 + sv.x) * iw;
        ov.y = (r1 + sv.y) * iw;
        ov.z = (r2 + sv.z) * iw;
        ov.w = (r3 + sv.w) * iw;
        og[i] = ov;
    }
}

// ---------------------------------------------------------------------------
// inputs: 0:x 1:core 2:out_f0 3:out_f1 4:out_f2 5:in_f0 6:in_f1 7:in_f2 8:mask
// ---------------------------------------------------------------------------
extern "C" void kernel_launch(void* const* d_in, const int* in_sizes, int n_in,
                              void* d_out, int out_size)
{
    const float* x      = (const float*)d_in[0];
    const float* core   = (const float*)d_in[1];
    const float* out_f0 = (const float*)d_in[2];
    const float* out_f1 = (const float*)d_in[3];
    const float* out_f2 = (const float*)d_in[4];
    const float* in_f0  = (const float*)d_in[5];
    const float* in_f1  = (const float*)d_in[6];
    const float* in_f2  = (const float*)d_in[7];
    float* out = (float*)d_out;

    k0_detect_mask<<<1, 1024>>>((const unsigned char*)d_in[8]);
    p1_foldA<<<1024, 256>>>(core, out_f0);
    p2_foldB<<<1024, 256>>>(out_f1);
    p3_foldD<<<1024, 256>>>(in_f0);
    p4_foldE<<<1024, 256>>>(in_f1);
    k1_reduce_project<<<GROUPS, 256>>>(x, in_f2);
    dim3 g2(GROUPS / 64, RRR / 64);
    k2_core_gemm<<<g2, 256>>>();
    k3_stream<<<GROUPS, 256>>>(out_f2, d_in[8], out);
}

// round 4
// speedup vs baseline: 1.0490x; 1.0490x over previous
#include <cuda_runtime.h>
#include <cstdint>

#define GROUPS  2048
#define MM      64
#define CC      128
#define TOK     8192
#define RK      8
#define RRR     512
#define SPITCH  129
#define MASKN   524288

__device__ float g_s [(size_t)GROUPS * TOK];  // 64 MB group sums
__device__ float g_t1[(size_t)GROUPS * RRR];  // 4 MB
__device__ float g_u2[(size_t)GROUPS * RRR];  // 4 MB
__device__ float g_w4[RRR * RRR];             // 1 MB folded operator
__device__ int   g_maskmode;

// ---------------------------------------------------------------------------
// Kernel 0: detect mask dtype (bool marshalled as u8/i32/f32).
// ---------------------------------------------------------------------------
__global__ void __launch_bounds__(1024) k0_detect_mask(const unsigned char* __restrict__ mask)
{
    __shared__ int s_ge2, s_odd;
    if (threadIdx.x == 0) { s_ge2 = 0; s_odd = 0; }
    __syncthreads();
    const uint4* p = (const uint4*)mask;
    unsigned acc = 0;
    for (int i = threadIdx.x; i < MASKN / 16; i += 1024) {
        uint4 v = p[i];
        acc |= (v.x | v.y | v.z | v.w);
    }
    if (acc & 0xFEFEFEFEu) atomicOr(&s_ge2, 1);
    if (acc & 0xFFFFFF00u) atomicOr(&s_odd, 1);
    __syncthreads();
    if (threadIdx.x == 0) g_maskmode = s_ge2 ? 2 : (s_odd ? 1 : 0);
}

// ---------------------------------------------------------------------------
// Fold kernel: W4[(o,p,C),(a,d,F)] = sum_{A,B,D,E} of0[o,A] of1[p,B] if0[a,D]
// if1[d,E] core[A,B,C,D,E,F].  One block per (C,F) pair: 64 blocks, all four
// 8-length contractions done in smem.
// ---------------------------------------------------------------------------
__global__ void __launch_bounds__(256) fold_w4(
    const float* __restrict__ core,
    const float* __restrict__ of0, const float* __restrict__ of1,
    const float* __restrict__ if0, const float* __restrict__ if1)
{
    __shared__ float bufA[4096], bufB[4096];
    __shared__ float sf[4][64];
    const int tid = threadIdx.x;
    const int C = blockIdx.x >> 3, F = blockIdx.x & 7;

    if (tid < 64)       sf[0][tid]       = of0[tid];
    else if (tid < 128) sf[1][tid - 64]  = of1[tid - 64];
    else if (tid < 192) sf[2][tid - 128] = if0[tid - 128];
    else                sf[3][tid - 192] = if1[tid - 192];

    // load K[A,B,D,E] slice for fixed (C,F)
    #pragma unroll
    for (int i = tid; i < 4096; i += 256) {
        int A = i >> 9, B = (i >> 6) & 7, D = (i >> 3) & 7, E = i & 7;
        bufA[i] = core[A * 32768 + B * 4096 + C * 512 + D * 64 + E * 8 + F];
    }
    __syncthreads();

    // M1[A,B,D,d] = sum_E K[A,B,D,E] * if1[d,E]
    #pragma unroll
    for (int i = tid; i < 4096; i += 256) {
        int ABD = i >> 3, d = i & 7;
        float acc = 0.f;
        #pragma unroll
        for (int E = 0; E < 8; E++) acc += bufA[ABD * 8 + E] * sf[3][d * 8 + E];
        bufB[i] = acc;
    }
    __syncthreads();

    // M2[A,B,d,a] = sum_D M1[A,B,D,d] * if0[a,D]
    #pragma unroll
    for (int i = tid; i < 4096; i += 256) {
        int AB = i >> 6, d = (i >> 3) & 7, a = i & 7;
        float acc = 0.f;
        #pragma unroll
        for (int D = 0; D < 8; D++) acc += bufB[(AB * 8 + D) * 8 + d] * sf[2][a * 8 + D];
        bufA[i] = acc;
    }
    __syncthreads();

    // M3[B,d,a,o] = sum_A M2[A,B,d,a] * of0[o,A]
    #pragma unroll
    for (int i = tid; i < 4096; i += 256) {
        int B = i >> 9, d = (i >> 6) & 7, a = (i >> 3) & 7, o = i & 7;
        float acc = 0.f;
        #pragma unroll
        for (int A = 0; A < 8; A++)
            acc += bufA[((A * 8 + B) * 8 + d) * 8 + a] * sf[0][o * 8 + A];
        bufB[i] = acc;
    }
    __syncthreads();

    // W4 slice: out[(o*8+p)*8+C][a*64+d*8+F] = sum_B M3[B,d,a,o] * of1[p,B]
    #pragma unroll
    for (int i = tid; i < 4096; i += 256) {
        int o = i >> 9, p = (i >> 6) & 7, a = (i >> 3) & 7, d = i & 7;
        float acc = 0.f;
        #pragma unroll
        for (int B = 0; B < 8; B++)
            acc += bufB[((B * 8 + d) * 8 + a) * 8 + o] * sf[1][p * 8 + B];
        g_w4[(size_t)((o * 8 + p) * 8 + C) * RRR + a * 64 + d * 8 + F] = acc;
    }
}

// ---------------------------------------------------------------------------
// Kernel 1: s = sum of 4 tokens -> scratch; T1[m,F] = sum_e s[m,e]*in_f2[e,F].
// smem-tile reduction (pitch 129), one sync on the hot path.
// ---------------------------------------------------------------------------
__global__ void __launch_bounds__(256) k1_reduce_project(
    const float* __restrict__ x,
    const float* __restrict__ in_f2)   // (128,8)
{
    __shared__ float s[MM * SPITCH];
    __shared__ float f2s[CC * RK];
    __shared__ float t1s[RRR];

    const int tid = threadIdx.x;
    const size_t gidx = blockIdx.x;

    #pragma unroll
    for (int i = tid; i < CC * RK; i += 256) f2s[i] = in_f2[i];

    const float4* xb = (const float4*)(x + gidx * (size_t)(4 * TOK));
    float4*       sg = (float4*)(g_s + gidx * (size_t)TOK);
    #pragma unroll
    for (int it = 0; it < 8; it++) {
        int i = tid + it * 256;
        float4 v0 = xb[i];
        float4 v1 = xb[i + 2048];
        float4 v2 = xb[i + 4096];
        float4 v3 = xb[i + 6144];
        float4 r;
        r.x = (v0.x + v1.x) + (v2.x + v3.x);
        r.y = (v0.y + v1.y) + (v2.y + v3.y);
        r.z = (v0.z + v1.z) + (v2.z + v3.z);
        r.w = (v0.w + v1.w) + (v2.w + v3.w);
        sg[i] = r;
        int m = i >> 5;
        int e = (i & 31) << 2;
        float* sp = &s[m * SPITCH + e];
        sp[0] = r.x; sp[1] = r.y; sp[2] = r.z; sp[3] = r.w;
    }
    __syncthreads();

    // t1[m][F] : m = tid&63 (conflict-free rows), F pair warp-uniform
    {
        int m  = tid & 63;
        int F0 = (tid >> 6) << 1;
        float acc0 = 0.f, acc1 = 0.f;
        const float* srow = &s[m * SPITCH];
        #pragma unroll 8
        for (int e = 0; e < CC; e++) {
            float sv = srow[e];
            acc0 += sv * f2s[e * RK + F0];
            acc1 += sv * f2s[e * RK + F0 + 1];
        }
        t1s[m * 8 + F0]     = acc0;
        t1s[m * 8 + F0 + 1] = acc1;
    }
    __syncthreads();
    float4* t1g = (float4*)(g_t1 + gidx * (size_t)RRR);
    if (tid < 128) t1g[tid] = ((const float4*)t1s)[tid];
}

// ---------------------------------------------------------------------------
// Kernel 2: U2 = T1 @ W4^T with packed fma.rn.f32x2 (Blackwell dual fp32).
// ---------------------------------------------------------------------------
__global__ void __launch_bounds__(256) k2_core_gemm()
{
    __shared__ __align__(16) float As[16][68];
    __shared__ __align__(16) float Bs[16][68];

    const int tid = threadIdx.x;
    const int bm = blockIdx.x * 64;
    const int bn = blockIdx.y * 64;
    const int tx = tid & 15, ty = tid >> 4;
    const int lr = tid >> 2;
    const int lk = (tid & 3) << 2;

    unsigned long long acc[4][2];
    #pragma unroll
    for (int i = 0; i < 4; i++) { acc[i][0] = 0ULL; acc[i][1] = 0ULL; }

    for (int k0 = 0; k0 < RRR; k0 += 16) {
        float4 av = *(const float4*)(g_t1 + (size_t)(bm + lr) * RRR + k0 + lk);
        float4 bv = *(const float4*)(g_w4 + (size_t)(bn + lr) * RRR + k0 + lk);
        __syncthreads();
        As[lk + 0][lr] = av.x; As[lk + 1][lr] = av.y;
        As[lk + 2][lr] = av.z; As[lk + 3][lr] = av.w;
        Bs[lk + 0][lr] = bv.x; Bs[lk + 1][lr] = bv.y;
        Bs[lk + 2][lr] = bv.z; Bs[lk + 3][lr] = bv.w;
        __syncthreads();
        #pragma unroll
        for (int k = 0; k < 16; k++) {
            unsigned long long b0 = *(const unsigned long long*)&Bs[k][tx * 4];
            unsigned long long b1 = *(const unsigned long long*)&Bs[k][tx * 4 + 2];
            #pragma unroll
            for (int i = 0; i < 4; i++) {
                float a = As[k][ty * 4 + i];
                unsigned long long ap;
                asm("mov.b64 %0, {%1, %1};" : "=l"(ap) : "f"(a));
                asm("fma.rn.f32x2 %0, %1, %2, %0;" : "+l"(acc[i][0]) : "l"(ap), "l"(b0));
                asm("fma.rn.f32x2 %0, %1, %2, %0;" : "+l"(acc[i][1]) : "l"(ap), "l"(b1));
            }
        }
    }
    #pragma unroll
    for (int i = 0; i < 4; i++) {
        *(unsigned long long*)&g_u2[(size_t)(bm + ty * 4 + i) * RRR + bn + tx * 4]     = acc[i][0];
        *(unsigned long long*)&g_u2[(size_t)(bm + ty * 4 + i) * RRR + bn + tx * 4 + 2] = acc[i][1];
    }
}

// ---------------------------------------------------------------------------
// Kernel 3: out[m][q] = (sum_C u2[m*8+C]*out_f2[q,C] + s[m][q]) * invw[m]
// ---------------------------------------------------------------------------
__global__ void __launch_bounds__(256) k3_stream(
    const float* __restrict__ out_f2,
    const void*  __restrict__ maskp,
    float* __restrict__ out)
{
    __shared__ float f2t[RK * CC];   // f2t[C*128+q]
    __shared__ float u2s[RRR];
    __shared__ float invw[MM];

    const int tid = threadIdx.x;
    const size_t gidx = blockIdx.x;

    if (tid < 128)
        ((float4*)u2s)[tid] = ((const float4*)(g_u2 + gidx * (size_t)RRR))[tid];
    #pragma unroll
    for (int i = tid; i < RK * CC; i += 256) {
        int q = i >> 3, Cr = i & 7;
        f2t[Cr * CC + q] = out_f2[i];
    }
    if (tid < 64) {
        int mode = g_maskmode;
        int w;
        if (mode == 1) {
            const unsigned char* mb = (const unsigned char*)maskp + gidx * (size_t)256;
            w = (mb[tid] ? 0 : 1) + (mb[tid + 64] ? 0 : 1)
              + (mb[tid + 128] ? 0 : 1) + (mb[tid + 192] ? 0 : 1);
        } else if (mode == 0) {
            const int* mi = (const int*)maskp + gidx * (size_t)256;
            w = (mi[tid] ? 0 : 1) + (mi[tid + 64] ? 0 : 1)
              + (mi[tid + 128] ? 0 : 1) + (mi[tid + 192] ? 0 : 1);
        } else {
            const float* mf = (const float*)maskp + gidx * (size_t)256;
            w = (mf[tid] != 0.f ? 0 : 1) + (mf[tid + 64] != 0.f ? 0 : 1)
              + (mf[tid + 128] != 0.f ? 0 : 1) + (mf[tid + 192] != 0.f ? 0 : 1);
        }
        invw[tid] = (w > 0) ? 1.0f / ((float)w + 1e-10f) : 0.0f;
    }
    __syncthreads();

    const float4* sg = (const float4*)(g_s + gidx * (size_t)TOK);
    float4*       og = (float4*)(out + gidx * (size_t)TOK);
    #pragma unroll
    for (int it = 0; it < 8; it++) {
        int i  = tid + it * 256;
        int m  = i >> 5;
        int q0 = (i & 31) << 2;
        float4 sv = sg[i];
        float r0 = 0.f, r1 = 0.f, r2 = 0.f, r3 = 0.f;
        #pragma unroll
        for (int Cr = 0; Cr < 8; Cr++) {
            float u = u2s[m * 8 + Cr];
            float4 f = *(const float4*)&f2t[Cr * CC + q0];
            r0 += u * f.x; r1 += u * f.y; r2 += u * f.z; r3 += u * f.w;
        }
        float iw = invw[m];
        float4 ov;
        ov.x = (r0 + sv.x) * iw;
        ov.y = (r1 + sv.y) * iw;
        ov.z = (r2 + sv.z) * iw;
        ov.w = (r3 + sv.w) * iw;
        og[i] = ov;
    }
}

// ---------------------------------------------------------------------------
// inputs: 0:x 1:core 2:out_f0 3:out_f1 4:out_f2 5:in_f0 6:in_f1 7:in_f2 8:mask
// ---------------------------------------------------------------------------
extern "C" void kernel_launch(void* const* d_in, const int* in_sizes, int n_in,
                              void* d_out, int out_size)
{
    const float* x      = (const float*)d_in[0];
    const float* core   = (const float*)d_in[1];
    const float* out_f0 = (const float*)d_in[2];
    const float* out_f1 = (const float*)d_in[3];
    const float* out_f2 = (const float*)d_in[4];
    const float* in_f0  = (const float*)d_in[5];
    const float* in_f1  = (const float*)d_in[6];
    const float* in_f2  = (const float*)d_in[7];
    float* out = (float*)d_out;

    k0_detect_mask<<<1, 1024>>>((const unsigned char*)d_in[8]);
    fold_w4<<<64, 256>>>(core, out_f0, out_f1, in_f0, in_f1);
    k1_reduce_project<<<GROUPS, 256>>>(x, in_f2);
    dim3 g2(GROUPS / 64, RRR / 64);
    k2_core_gemm<<<g2, 256>>>();
    k3_stream<<<GROUPS, 256>>>(out_f2, d_in[8], out);
}